// round 2
// baseline (speedup 1.0000x reference)
#include <cuda_runtime.h>

// ---------------------------------------------------------------------------
// AttentionShareLocal: Swin window attention, fp32.
//   B=2048 windows, N=49, C=256 (8 heads x d=32).
//   S = QK^T * d^-0.5 + bias[h];  P = softmax(S);  O = P V
// R2 design: 224 thr/CTA, 2 heads/CTA, 3 CTAs/SM (21 warps).
//   QK: 5x5 packed-f32x2 register tiles (d-paired partial sums).
//   PV: 4x4 tiles, j-paired partial sums against V^T in smem (no splats).
// ---------------------------------------------------------------------------

#define NPOS     169
#define NH       8
#define HPB      2
#define NTOK     49
#define QK_STR   36          // q/k row stride (mult of 4 -> float4 stores ok)
#define S_STR    50          // S: 50x50 per head (padded, even for u64)
#define VT_STR   50          // V^T: 32 x 50 per head
#define THREADS  224

__device__ float g_pos[NPOS * NH];

// ---------------- bias table kernel ----------------------------------------
__global__ void bias_kernel(const float* __restrict__ W1, const float* __restrict__ b1,
                            const float* __restrict__ W2, const float* __restrict__ b2) {
    int p = threadIdx.x;
    if (p >= NPOS) return;
    float bh = (float)(p / 13 - 6);
    float bw = (float)(p % 13 - 6);
    float acc[NH];
#pragma unroll
    for (int h = 0; h < NH; h++) acc[h] = b2[h];
    for (int k = 0; k < 64; k++) {
        float hv = fmaf(bh, W1[k], fmaf(bw, W1[64 + k], b1[k]));
        hv = fmaxf(hv, 0.0f);
#pragma unroll
        for (int h = 0; h < NH; h++) acc[h] = fmaf(hv, W2[k * NH + h], acc[h]);
    }
#pragma unroll
    for (int h = 0; h < NH; h++) g_pos[p * NH + h] = acc[h];
}

// ---------------- packed f32x2 helpers --------------------------------------
typedef unsigned long long u64;

__device__ __forceinline__ void fma2(u64& d, u64 a, u64 b) {
    asm("fma.rn.f32x2 %0, %1, %2, %0;" : "+l"(d) : "l"(a), "l"(b));
}
__device__ __forceinline__ float2 unpack2(u64 x) {
    float2 r;
    asm("mov.b64 {%0, %1}, %2;" : "=f"(r.x), "=f"(r.y) : "l"(x));
    return r;
}

// ---------------- main fused attention kernel -------------------------------
__global__ __launch_bounds__(THREADS, 3)
void attn_kernel(const float* __restrict__ Q, const float* __restrict__ K,
                 const float* __restrict__ V, float* __restrict__ O) {
    extern __shared__ float sm[];
    float* sQ   = sm;                                   // 2*49*36 = 3528
    float* sK   = sQ  + HPB * NTOK * QK_STR;            // 3528
    float* sVT  = sK  + HPB * NTOK * QK_STR;            // 2*32*50 = 3200
    float* sS   = sVT + HPB * 32 * VT_STR;              // 2*50*50 = 5000
    float* sPos = sS  + HPB * S_STR * S_STR;            // 338
    float* sInv = sPos + HPB * NPOS;                    // 98

    const int t  = threadIdx.x;
    const int b  = blockIdx.x >> 2;
    const int hb = blockIdx.x & 3;                      // head-pair 0..3

    const long gbase = (long)b * (NTOK * 256) + hb * (HPB * 32);

    // -------- Phase 1: stage Q,K row-major; V transposed; pos; padding ------
    for (int idx = t; idx < 1568; idx += THREADS) {     // Q and K
        int tsel = idx / 784;
        int rem  = idx - tsel * 784;
        int r    = rem >> 4;
        int c4   = rem & 15;
        const float* src = (tsel ? K : Q) + gbase + r * 256 + c4 * 4;
        float4 val = *(const float4*)src;
        int hh = c4 >> 3;
        int kk = (c4 & 7) * 4;
        float* dst = (tsel ? sK : sQ) + (hh * NTOK + r) * QK_STR + kk;
        *(float4*)dst = val;
    }
    for (int idx = t; idx < 784; idx += THREADS) {      // V -> V^T
        int r  = idx >> 4;
        int c4 = idx & 15;
        float4 val = *(const float4*)(V + gbase + r * 256 + c4 * 4);
        int hh = c4 >> 3;
        int d0 = (c4 & 7) * 4;
        float* dst = sVT + (hh * 32 + d0) * VT_STR + r;
        dst[0 * VT_STR] = val.x;
        dst[1 * VT_STR] = val.y;
        dst[2 * VT_STR] = val.z;
        dst[3 * VT_STR] = val.w;
    }
    if (t < 64) {                                       // zero V^T pad col j=49
        int hh = t >> 5, d = t & 31;
        sVT[(hh * 32 + d) * VT_STR + NTOK] = 0.0f;
    }
    for (int idx = t; idx < HPB * NPOS; idx += THREADS) {
        int hh = idx / NPOS, p = idx - hh * NPOS;
        sPos[hh * NPOS + p] = g_pos[p * NH + hb * HPB + hh];
    }
    __syncthreads();

    // -------- Phase 2: S = QK^T*scale + bias  (5i x 5j tiles, 200 threads) --
    if (t < HPB * 100) {
        int h    = t / 100;
        int r    = t - h * 100;
        int igrp = r / 10;
        int jgrp = r - igrp * 10;
        int i0 = igrp * 5;
        int j0 = jgrp * 5;

        const float* qh = sQ + (h * NTOK + i0) * QK_STR;
        const float* kh = sK + h * NTOK * QK_STR;
        const float* kp[5];
#pragma unroll
        for (int w = 0; w < 5; w++) {
            int j = j0 + w; if (j > 48) j = 48;
            kp[w] = kh + j * QK_STR;
        }

        u64 acc[5][5];
#pragma unroll
        for (int u = 0; u < 5; u++)
#pragma unroll
            for (int w = 0; w < 5; w++) acc[u][w] = 0ull;

#pragma unroll 8
        for (int kpp = 0; kpp < 16; kpp++) {
            u64 q2[5], k2[5];
#pragma unroll
            for (int u = 0; u < 5; u++) q2[u] = *(const u64*)(qh + u * QK_STR + kpp * 2);
#pragma unroll
            for (int w = 0; w < 5; w++) k2[w] = *(const u64*)(kp[w] + kpp * 2);
#pragma unroll
            for (int u = 0; u < 5; u++)
#pragma unroll
                for (int w = 0; w < 5; w++) fma2(acc[u][w], q2[u], k2[w]);
        }

        const float scale = 0.17677669529663687f;       // 32^-0.5
        float* sb = sS + h * S_STR * S_STR;
        const float* ph = sPos + h * NPOS;
#pragma unroll
        for (int u = 0; u < 5; u++) {
            int i = i0 + u;
            if (i < NTOK) {
                int fi = i + 6 * (i / 7);
#pragma unroll
                for (int w = 0; w < 5; w++) {
                    int j = j0 + w;
                    if (j < NTOK) {
                        int fj = j + 6 * (j / 7);
                        float2 a = unpack2(acc[u][w]);
                        sb[i * S_STR + j] = (a.x + a.y) * scale + ph[fi - fj + 84];
                    }
                }
            }
        }
    }
    __syncthreads();

    // -------- Phase 3: softmax rows; zero pad col; stash 1/sum --------------
    if (t < HPB * NTOK) {
        int h = t / NTOK, i = t - h * NTOK;
        float* row = sS + (h * S_STR + i) * S_STR;
        float m = row[0];
#pragma unroll 7
        for (int j = 1; j < NTOK; j++) m = fmaxf(m, row[j]);
        float sum = 0.0f;
#pragma unroll 7
        for (int j = 0; j < NTOK; j++) {
            float e = exp2f((row[j] - m) * 1.4426950408889634f);
            row[j] = e;
            sum += e;
        }
        row[NTOK] = 0.0f;                                // pad j=49
        sInv[h * NTOK + i] = __frcp_rn(sum);
    }
    __syncthreads();

    // -------- Phase 4: O = P V  (4i x 4d tiles, j-paired, 208 threads) ------
    if (t < HPB * 104) {
        int h    = t / 104;
        int r    = t - h * 104;
        int igrp = r >> 3;                               // 0..12
        int dgrp = r & 7;                                // 0..7
        int i0 = igrp * 4;
        int d0 = dgrp * 4;

        const float* Pp = sS  + (h * S_STR + i0) * S_STR;
        const float* vt = sVT + (h * 32 + d0) * VT_STR;

        u64 acc[4][4];
#pragma unroll
        for (int u = 0; u < 4; u++)
#pragma unroll
            for (int w = 0; w < 4; w++) acc[u][w] = 0ull;

#pragma unroll 5
        for (int jp = 0; jp < 25; jp++) {
            u64 p2[4], v2[4];
#pragma unroll
            for (int u = 0; u < 4; u++) p2[u] = *(const u64*)(Pp + u * S_STR + jp * 2);
#pragma unroll
            for (int w = 0; w < 4; w++) v2[w] = *(const u64*)(vt + w * VT_STR + jp * 2);
#pragma unroll
            for (int u = 0; u < 4; u++)
#pragma unroll
                for (int w = 0; w < 4; w++) fma2(acc[u][w], p2[u], v2[w]);
        }

        float* outp = O + (long)b * (NTOK * 256) + hb * (HPB * 32) + h * 32 + d0;
#pragma unroll
        for (int u = 0; u < 4; u++) {
            int i = i0 + u;
            if (i < NTOK) {
                float inv = sInv[h * NTOK + i];
                float4 o;
                float2 a0 = unpack2(acc[u][0]);
                float2 a1 = unpack2(acc[u][1]);
                float2 a2 = unpack2(acc[u][2]);
                float2 a3 = unpack2(acc[u][3]);
                o.x = (a0.x + a0.y) * inv;
                o.y = (a1.x + a1.y) * inv;
                o.z = (a2.x + a2.y) * inv;
                o.w = (a3.x + a3.y) * inv;
                *(float4*)(outp + i * 256) = o;
            }
        }
    }
}

// ---------------------------------------------------------------------------
extern "C" void kernel_launch(void* const* d_in, const int* in_sizes, int n_in,
                              void* d_out, int out_size) {
    const float* q  = (const float*)d_in[0];
    const float* k  = (const float*)d_in[1];
    const float* v  = (const float*)d_in[2];
    const float* W1 = (const float*)d_in[3];
    const float* b1 = (const float*)d_in[4];
    const float* W2 = (const float*)d_in[5];
    const float* b2 = (const float*)d_in[6];
    float* out = (float*)d_out;

    int B = in_sizes[0] / (NTOK * 256);

    const int smem_floats = 2 * HPB * NTOK * QK_STR      // sQ, sK
                          + HPB * 32 * VT_STR            // sVT
                          + HPB * S_STR * S_STR          // sS
                          + HPB * NPOS                   // sPos
                          + HPB * NTOK;                  // sInv
    const int smem_bytes = smem_floats * (int)sizeof(float);

    cudaFuncSetAttribute(attn_kernel, cudaFuncAttributeMaxDynamicSharedMemorySize, smem_bytes);

    bias_kernel<<<1, 192>>>(W1, b1, W2, b2);
    attn_kernel<<<B * (NH / HPB), THREADS, smem_bytes>>>(q, k, v, out);
}